// round 3
// baseline (speedup 1.0000x reference)
#include <cuda_runtime.h>

#define NN 50000
#define EE 800000
#define ET 850000   // EE + NN self-loops

// ---------------- scratch (device globals; no runtime allocation) ----------
__device__ int   g_deg[NN];
__device__ int   g_cur[NN];
__device__ int   g_off[NN + 1];
__device__ float g_dis[NN];
__device__ int   g_rowE[EE];
__device__ int   g_colE[EE];
__device__ int   g_src[ET];
__device__ float g_w[ET];
__device__ float g_bufA[(size_t)NN * 128];
__device__ float g_bufB[(size_t)NN * 128];

// Compile-time buffer selector: internal buffers referenced directly from
// device code (no host-side symbol lookup).
enum Which { A_, B_, X_ };

template <Which W>
__device__ __forceinline__ const float* inbuf(const float* ext) {
    if constexpr (W == A_) return g_bufA;
    else if constexpr (W == B_) return g_bufB;
    else return ext;
}
template <Which W>
__device__ __forceinline__ float* outbuf(float* ext) {
    if constexpr (W == A_) return g_bufA;
    else if constexpr (W == B_) return g_bufB;
    else return ext;
}

// ---------------- graph prep kernels ---------------------------------------
__global__ void k_zero() {
    int i = blockIdx.x * blockDim.x + threadIdx.x;
    if (i < NN) { g_deg[i] = 0; g_cur[i] = 0; }
}

// edge_index is int32 (JAX x64 is disabled; jnp.int64 silently downcasts).
__global__ void k_count(const int* __restrict__ ei) {
    int e = blockIdx.x * blockDim.x + threadIdx.x;
    if (e >= EE) return;
    int r = ei[e];
    int c = ei[EE + e];
    // defensive: never trap on a bad index (no-op for valid data)
    if ((unsigned)r >= NN) r = 0;
    if ((unsigned)c >= NN) c = 0;
    g_rowE[e] = r;
    g_colE[e] = c;
    atomicAdd(&g_deg[c], 1);
}

__global__ void k_dis() {
    int i = blockIdx.x * blockDim.x + threadIdx.x;
    if (i < NN) g_dis[i] = rsqrtf((float)(g_deg[i] + 1));   // +1 = self loop
}

// exclusive scan of (deg[i]+1) into g_off, single block of 1024 threads
__global__ void k_scan() {
    const int tid = threadIdx.x, lane = tid & 31, wid = tid >> 5;
    __shared__ int wexcl[32];
    __shared__ int carry;
    __shared__ int chunktot;
    if (tid == 0) carry = 0;
    __syncthreads();
    for (int base = 0; base < NN; base += 1024) {
        int i = base + tid;
        int v = (i < NN) ? (g_deg[i] + 1) : 0;
        int incl = v;
#pragma unroll
        for (int o = 1; o < 32; o <<= 1) {
            int t = __shfl_up_sync(0xffffffffu, incl, o);
            if (lane >= o) incl += t;
        }
        if (lane == 31) wexcl[wid] = incl;
        __syncthreads();
        if (wid == 0) {
            int wv = wexcl[lane];
            int wincl = wv;
#pragma unroll
            for (int o = 1; o < 32; o <<= 1) {
                int t = __shfl_up_sync(0xffffffffu, wincl, o);
                if (lane >= o) wincl += t;
            }
            wexcl[lane] = wincl - wv;
            if (lane == 31) chunktot = wincl;
        }
        __syncthreads();
        if (i < NN) g_off[i] = carry + wexcl[wid] + (incl - v);
        __syncthreads();
        if (tid == 0) carry += chunktot;
        __syncthreads();
    }
    if (tid == 0) g_off[NN] = carry;
}

__global__ void k_fill() {
    int e = blockIdx.x * blockDim.x + threadIdx.x;
    if (e >= EE) return;
    int r = g_rowE[e], c = g_colE[e];
    int p = atomicAdd(&g_cur[c], 1);
    int idx = g_off[c] + p;
    g_src[idx] = r;
    g_w[idx] = g_dis[r] * g_dis[c];
}

__global__ void k_self() {
    int n = blockIdx.x * blockDim.x + threadIdx.x;
    if (n >= NN) return;
    int idx = g_off[n + 1] - 1;     // last slot of each segment reserved
    g_src[idx] = n;
    float d = g_dis[n];
    g_w[idx] = d * d;
}

// ---------------- aggregation: out[n] = (bias) + sum_e w_e * h[src_e] ------
template <int F, bool BIAS, Which SRC, Which DST>
__global__ __launch_bounds__(256) void k_agg(const float* __restrict__ ext_in,
                                             const float* __restrict__ b,
                                             float* __restrict__ ext_out) {
    const float* __restrict__ h = inbuf<SRC>(ext_in);
    float* __restrict__ out = outbuf<DST>(ext_out);
    constexpr int NACC = (F + 31) / 32;
    int warp = (blockIdx.x * blockDim.x + threadIdx.x) >> 5;
    int lane = threadIdx.x & 31;
    if (warp >= NN) return;
    int n = warp;
    int s = g_off[n], e = g_off[n + 1];
    float acc[NACC];
#pragma unroll
    for (int j = 0; j < NACC; j++) acc[j] = 0.f;
    for (int i = s; i < e; i++) {
        int src = g_src[i];
        float w = g_w[i];
        const float* hp = h + (size_t)src * F;
#pragma unroll
        for (int j = 0; j < NACC; j++) {
            int f = lane + 32 * j;
            if (f < F) acc[j] += w * __ldg(hp + f);
        }
    }
    float* op = out + (size_t)n * F;
#pragma unroll
    for (int j = 0; j < NACC; j++) {
        int f = lane + 32 * j;
        if (f < F) op[f] = acc[j] + (BIAS ? b[f] : 0.f);
    }
}

// ---------------- GEMM: out[n][o] = (bias[o]) + sum_k x[n][k]*W[k][o] ------
template <int IN, int OUT, bool BIAS, bool RELU, Which SRC, Which DST>
__global__ void k_gemm(const float* __restrict__ ext_in,
                       const float* __restrict__ W,
                       const float* __restrict__ b,
                       float* __restrict__ ext_out) {
    const float* __restrict__ x = inbuf<SRC>(ext_in);
    float* __restrict__ out = outbuf<DST>(ext_out);
    constexpr int YB = 256 / OUT;       // 96->2,128->2,64->4,32->8
    constexpr int NPT = 4;              // nodes per thread
    __shared__ float Ws[IN * OUT];
    for (int i = threadIdx.x; i < IN * OUT; i += blockDim.x) Ws[i] = W[i];
    __syncthreads();
    int o = threadIdx.x % OUT;
    int yy = threadIdx.x / OUT;
    int nodeBase = (blockIdx.x * YB + yy) * NPT;
    if (nodeBase >= NN) return;
    float acc[NPT];
    float bias = BIAS ? b[o] : 0.f;
#pragma unroll
    for (int j = 0; j < NPT; j++) acc[j] = 0.f;
    const float* xr = x + (size_t)nodeBase * IN;
    if (nodeBase + NPT <= NN) {
#pragma unroll
        for (int k = 0; k < IN; k++) {
            float w = Ws[k * OUT + o];
#pragma unroll
            for (int j = 0; j < NPT; j++) acc[j] += xr[(size_t)j * IN + k] * w;
        }
#pragma unroll
        for (int j = 0; j < NPT; j++) {
            float v = acc[j] + bias;
            out[(size_t)(nodeBase + j) * OUT + o] = RELU ? fmaxf(v, 0.f) : v;
        }
    } else {
        for (int k = 0; k < IN; k++) {
            float w = Ws[k * OUT + o];
#pragma unroll
            for (int j = 0; j < NPT; j++)
                if (nodeBase + j < NN) acc[j] += xr[(size_t)j * IN + k] * w;
        }
#pragma unroll
        for (int j = 0; j < NPT; j++)
            if (nodeBase + j < NN) {
                float v = acc[j] + bias;
                out[(size_t)(nodeBase + j) * OUT + o] = RELU ? fmaxf(v, 0.f) : v;
            }
    }
}

// ---------------- launch ----------------------------------------------------
static inline int ceil_div(int a, int b) { return (a + b - 1) / b; }

extern "C" void kernel_launch(void* const* d_in, const int* in_sizes, int n_in,
                              void* d_out, int out_size) {
    const float* x  = (const float*)d_in[0];
    const int*   ei = (const int*)d_in[1];   // int32 edge_index (2, E) flattened
    const float* W1 = (const float*)d_in[2]; const float* b1 = (const float*)d_in[3];
    const float* W2 = (const float*)d_in[4]; const float* b2 = (const float*)d_in[5];
    const float* W3 = (const float*)d_in[6]; const float* b3 = (const float*)d_in[7];
    const float* W4 = (const float*)d_in[8]; const float* b4 = (const float*)d_in[9];
    float* out = (float*)d_out;

    const int TB = 256;
    const int gN = ceil_div(NN, TB);
    const int gE = ceil_div(EE, TB);
    const int gW = ceil_div(NN, TB / 32);   // one warp per node

    // graph prep
    k_zero<<<gN, TB>>>();
    k_count<<<gE, TB>>>(ei);
    k_dis<<<gN, TB>>>();
    k_scan<<<1, 1024>>>();
    k_fill<<<gE, TB>>>();
    k_self<<<gN, TB>>>();

    // layer 1: h1 = relu((A x) W1 + b1)   — aggregate 29 feats, then GEMM
    k_agg<29, false, X_, A_><<<gW, TB>>>(x, nullptr, nullptr);
    k_gemm<29, 96, true, true, A_, B_>
        <<<ceil_div(NN, (256/96)*4), (256/96)*96>>>(nullptr, W1, b1, nullptr);

    // layer 2: h2 = (A h1) W2 + b2       — aggregate 96 feats, then GEMM
    k_agg<96, false, B_, A_><<<gW, TB>>>(nullptr, nullptr, nullptr);
    k_gemm<96, 128, true, false, A_, B_>
        <<<ceil_div(NN, (256/128)*4), 256>>>(nullptr, W2, b2, nullptr);

    // layer 3: h3 = A (h2 W3) + b3       — GEMM first (64 < 128), agg with bias
    k_gemm<128, 64, false, false, B_, A_>
        <<<ceil_div(NN, (256/64)*4), 256>>>(nullptr, W3, nullptr, nullptr);
    k_agg<64, true, A_, B_><<<gW, TB>>>(nullptr, b3, nullptr);

    // layer 4: out = A (h3 W4) + b4      — GEMM first (32 < 64), agg with bias
    k_gemm<64, 32, false, false, B_, A_>
        <<<ceil_div(NN, (256/32)*4), 256>>>(nullptr, W4, nullptr, nullptr);
    k_agg<32, true, A_, X_><<<gW, TB>>>(nullptr, b4, out);

    (void)in_sizes; (void)n_in; (void)out_size;
}